// round 10
// baseline (speedup 1.0000x reference)
#include <cuda_runtime.h>
#include <cuda_fp16.h>
#include <cstdint>

// S4 kernel materialization on HMMA (mma.sync m16n8k16 fp16):
//   K[h,l] = 2*Re( sum_n Cc_n z_n^l ),  z = exp(dtA), Cc = C*(z-1)/A
// l = 64q + r -> per-h GEMM D[64q][64r] = A[64x64] @ B[64x64]^T (K=64, j=2n re/im)
//   A row q: word n = (Re z^(64q), Im z^(64q))  -- fp16 hi/lo SPLIT (2 tiles)
//   B row r: word n = (2Re, -2Im) of Cc z^r     -- single fp16 tile
// D = Ahi*B + Alo*B  (fp32 accum).
// R10: fragment loads via ldmatrix.x4 (96 LDS.32 -> 24 ldmatrix per thread).

#define Hh   1024
#define NHn  32
#define Ll   4096

__device__ __forceinline__ uint32_t pack_h2(float re, float im) {
    __half2 v = __floats2half2_rn(re, im);   // low = re (k even), high = im (k odd)
    return *(uint32_t*)&v;
}

__device__ __forceinline__ void split_h2(float re, float im, uint32_t& hi, uint32_t& lo) {
    __half hr = __float2half_rn(re);
    __half hm = __float2half_rn(im);
    float lr = re - __half2float(hr);
    float lm = im - __half2float(hm);
    __half2 hv; hv.x = hr; hv.y = hm;
    hi = *(uint32_t*)&hv;
    lo = pack_h2(lr, lm);
}

__device__ __forceinline__ void mma16816(float* c, const uint32_t* a,
                                         uint32_t b0, uint32_t b1) {
    asm volatile(
        "mma.sync.aligned.m16n8k16.row.col.f32.f16.f16.f32 "
        "{%0,%1,%2,%3}, {%4,%5,%6,%7}, {%8,%9}, {%0,%1,%2,%3};"
        : "+f"(c[0]), "+f"(c[1]), "+f"(c[2]), "+f"(c[3])
        : "r"(a[0]), "r"(a[1]), "r"(a[2]), "r"(a[3]), "r"(b0), "r"(b1));
}

__device__ __forceinline__ void ldmx4(uint32_t* r, uint32_t addr) {
    asm volatile(
        "ldmatrix.sync.aligned.m8n8.x4.shared.b16 {%0,%1,%2,%3}, [%4];"
        : "=r"(r[0]), "=r"(r[1]), "=r"(r[2]), "=r"(r[3]) : "r"(addr));
}

__global__ __launch_bounds__(128, 7)
void s4_hmma_kernel(const float* __restrict__ Cin,        // [H, NH, 2]
                    const float* __restrict__ log_dt,     // [H]
                    const float* __restrict__ log_A_real, // [H, NH]
                    const float* __restrict__ A_imag,     // [H, NH]
                    float* __restrict__ out)              // [H, L]
{
    // 64 rows x 32 words (64 fp16) per tile, XOR swizzle: word = n ^ ((row&7)<<2)
    __shared__ uint32_t Ahi[64 * 32], Alo[64 * 32];
    __shared__ uint32_t Bt[64 * 32];

    const int h    = blockIdx.x;
    const int tid  = threadIdx.x;
    const int lane = tid & 31;
    const int w    = tid >> 5;

    // ---- phase 1: 4 chains x 8 steps per warp, balanced (R9, verified) ----
    {
        const int n = lane;

        float dt   = expf(log_dt[h]);
        float Are  = -expf(log_A_real[h * NHn + n]);
        float Aim  = -A_imag[h * NHn + n];
        float dtar = Are * dt;
        float dtai = Aim * dt;

        float er = expf(dtar);
        float sn, cs;
        sincosf(dtai, &sn, &cs);
        float zr = er * cs, zi = er * sn;            // z = exp(dtA)

        // Cc = C * (z-1)/A
        float nr = zr - 1.0f, ni = zi;
        float inv = 1.0f / (Are * Are + Aim * Aim);
        float fr = (nr * Are + ni * Aim) * inv;
        float fi = (ni * Are - nr * Aim) * inv;
        float c0 = Cin[(h * NHn + n) * 2 + 0];
        float c1 = Cin[(h * NHn + n) * 2 + 1];
        float ccr = c0 * fr - c1 * fi;
        float cci = c0 * fi + c1 * fr;

        // anchors by repeated squaring
        #define CSQ(r_, i_) { float t_ = r_*r_ - i_*i_; i_ = 2.0f*r_*i_; r_ = t_; }
        float z8r = zr, z8i = zi;
        CSQ(z8r, z8i) CSQ(z8r, z8i) CSQ(z8r, z8i)               // z^8
        float z16r = z8r, z16i = z8i;  CSQ(z16r, z16i)          // z^16
        float z32r = z16r, z32i = z16i; CSQ(z32r, z32i)         // z^32
        float z64r = z32r, z64i = z32i; CSQ(z64r, z64i)         // z^64
        float z512r = z64r, z512i = z64i;
        CSQ(z512r, z512i) CSQ(z512r, z512i) CSQ(z512r, z512i)   // z^512
        float z1024r = z512r, z1024i = z512i; CSQ(z1024r, z1024i)   // z^1024
        float z2048r = z1024r, z2048i = z1024i; CSQ(z2048r, z2048i) // z^2048
        #undef CSQ

        // z^(16w): {1, z16, z32, z16*z32}
        float pwr, pwi;
        if (w == 0)      { pwr = 1.0f;  pwi = 0.0f;  }
        else if (w == 1) { pwr = z16r;  pwi = z16i;  }
        else if (w == 2) { pwr = z32r;  pwi = z32i;  }
        else             { pwr = z16r * z32r - z16i * z32i;
                           pwi = z16r * z32i + z16i * z32r; }

        // z^(1024w): {1, z1024, z2048, z1024*z2048}
        float awr, awi;
        if (w == 0)      { awr = 1.0f;   awi = 0.0f;   }
        else if (w == 1) { awr = z1024r; awi = z1024i; }
        else if (w == 2) { awr = z2048r; awi = z2048i; }
        else             { awr = z1024r * z2048r - z1024i * z2048i;
                           awi = z1024r * z2048i + z1024i * z2048r; }

        // chain starts
        float s0r = ccr * pwr - cci * pwi;           // B row 16w   : Cc z^(16w)
        float s0i = ccr * pwi + cci * pwr;
        float s1r = s0r * z8r - s0i * z8i;           // B row 16w+8
        float s1i = s0r * z8i + s0i * z8r;
        float t0r = awr, t0i = awi;                  // A row 16w   : z^(1024w)
        float t1r = awr * z512r - awi * z512i;       // A row 16w+8
        float t1i = awr * z512i + awi * z512r;

        const int rowB0 = w * 16, rowB1 = w * 16 + 8;

        #pragma unroll
        for (int i = 0; i < 8; i++) {
            int rb0 = rowB0 + i, rb1 = rowB1 + i;
            Bt[rb0 * 32 + (n ^ ((rb0 & 7) << 2))] = pack_h2(2.0f * s0r, -2.0f * s0i);
            Bt[rb1 * 32 + (n ^ ((rb1 & 7) << 2))] = pack_h2(2.0f * s1r, -2.0f * s1i);
            uint32_t hi, lo;
            split_h2(t0r, t0i, hi, lo);
            { int wo = rb0 * 32 + (n ^ ((rb0 & 7) << 2)); Ahi[wo] = hi; Alo[wo] = lo; }
            split_h2(t1r, t1i, hi, lo);
            { int wo = rb1 * 32 + (n ^ ((rb1 & 7) << 2)); Ahi[wo] = hi; Alo[wo] = lo; }

            float t;
            t = s0r * zr - s0i * zi;     s0i = s0r * zi + s0i * zr;     s0r = t;
            t = s1r * zr - s1i * zi;     s1i = s1r * zi + s1i * zr;     s1r = t;
            t = t0r * z64r - t0i * z64i; t0i = t0r * z64i + t0i * z64r; t0r = t;
            t = t1r * z64r - t1i * z64i; t1i = t1r * z64i + t1i * z64r; t1r = t;
        }
    }
    __syncthreads();

    // ---- phase 2: MMA with ldmatrix fragment loads ----
    const int lane8 = lane & 7;
    const int g     = lane >> 3;          // ldmatrix matrix-group 0..3
    const uint32_t swx = (uint32_t)lane8 << 2;   // per-row XOR (row&7 == lane8)

    uint32_t aHiBase = (uint32_t)__cvta_generic_to_shared(Ahi);
    uint32_t aLoBase = (uint32_t)__cvta_generic_to_shared(Alo);
    uint32_t bBase   = (uint32_t)__cvta_generic_to_shared(Bt);

    // A: matrix g -> rows w*16 + (g&1)*8 + lane8, kword base (g>>1)*4
    const uint32_t aRow  = (uint32_t)(w * 16 + ((g & 1) << 3) + lane8);
    const uint32_t aOff0 = (aRow << 5) << 2;          // row * 32 words * 4B
    const uint32_t aKsel = (uint32_t)((g >> 1) << 2); // 0 or 4 words

    float acc[8][4];
    #pragma unroll
    for (int nt = 0; nt < 8; nt++)
        #pragma unroll
        for (int i = 0; i < 4; i++) acc[nt][i] = 0.0f;

    #pragma unroll
    for (int ks = 0; ks < 4; ks++) {
        uint32_t aw = (uint32_t)(ks * 8) + aKsel;     // word col, 4-aligned
        uint32_t aoff = aOff0 + ((aw ^ swx) << 2);
        uint32_t ah[4], al[4];
        ldmx4(ah, aHiBase + aoff);
        ldmx4(al, aLoBase + aoff);

        // B: pair p covers nt = 2p + (g>>1), khalf = g&1
        uint32_t b[16];
        #pragma unroll
        for (int p = 0; p < 4; p++) {
            uint32_t nt0 = (uint32_t)(2 * p + (g >> 1));
            uint32_t row = (nt0 << 3) + (uint32_t)lane8;
            uint32_t wc  = (uint32_t)(ks * 8) + ((uint32_t)(g & 1) << 2);
            uint32_t off = ((row << 5) << 2) + ((wc ^ swx) << 2);
            ldmx4(&b[p * 4], bBase + off);
        }

        #pragma unroll
        for (int nt = 0; nt < 8; nt++) {
            uint32_t b0 = b[nt * 2], b1 = b[nt * 2 + 1];
            mma16816(acc[nt], ah, b0, b1);
            mma16816(acc[nt], al, b0, b1);
        }
    }

    // ---- epilogue: D(q, r) -> out[h, 64q + r] ----
    const int lane4 = lane >> 2;
    const int kq    = lane & 3;
    const int q0 = w * 16 + lane4, q1 = q0 + 8;
    const int cb = kq * 2;
    float* o = out + (size_t)h * Ll;
    #pragma unroll
    for (int nt = 0; nt < 8; nt++) {
        int c = nt * 8 + cb;
        *(float2*)&o[q0 * 64 + c] = make_float2(acc[nt][0], acc[nt][1]);
        *(float2*)&o[q1 * 64 + c] = make_float2(acc[nt][2], acc[nt][3]);
    }
}

extern "C" void kernel_launch(void* const* d_in, const int* in_sizes, int n_in,
                              void* d_out, int out_size)
{
    const float* C          = (const float*)d_in[0];   // [H, NH, 2]
    const float* log_dt     = (const float*)d_in[1];   // [H]
    const float* log_A_real = (const float*)d_in[2];   // [H, NH]
    const float* A_imag     = (const float*)d_in[3];   // [H, NH]
    float* out              = (float*)d_out;           // [H, L]

    s4_hmma_kernel<<<Hh, 128>>>(C, log_dt, log_A_real, A_imag, out);
}

// round 11
// speedup vs baseline: 1.0030x; 1.0030x over previous
#include <cuda_runtime.h>
#include <cuda_fp16.h>
#include <cstdint>

// S4 kernel materialization on HMMA (mma.sync m16n8k16 fp16):
//   K[h,l] = 2*Re( sum_n Cc_n z_n^l ),  z = exp(dtA), Cc = C*(z-1)/A
// l = 64q + r -> per-h GEMM D[64q][64r] = A[64x64] @ B[64x64]^T (K=64, j=2n re/im)
// D = Ahi*B + Alo*B (fp32 accum), fp16 one-sided split.
// R11: fast intrinsics for exp/sincos head, 8 CTAs/SM, ldmatrix loads.

#define Hh   1024
#define NHn  32
#define Ll   4096

__device__ __forceinline__ uint32_t pack_h2(float re, float im) {
    __half2 v = __floats2half2_rn(re, im);   // low = re (k even), high = im (k odd)
    return *(uint32_t*)&v;
}

__device__ __forceinline__ void split_h2(float re, float im, uint32_t& hi, uint32_t& lo) {
    __half hr = __float2half_rn(re);
    __half hm = __float2half_rn(im);
    float lr = re - __half2float(hr);
    float lm = im - __half2float(hm);
    __half2 hv; hv.x = hr; hv.y = hm;
    hi = *(uint32_t*)&hv;
    lo = pack_h2(lr, lm);
}

__device__ __forceinline__ void mma16816(float* c, const uint32_t* a,
                                         uint32_t b0, uint32_t b1) {
    asm volatile(
        "mma.sync.aligned.m16n8k16.row.col.f32.f16.f16.f32 "
        "{%0,%1,%2,%3}, {%4,%5,%6,%7}, {%8,%9}, {%0,%1,%2,%3};"
        : "+f"(c[0]), "+f"(c[1]), "+f"(c[2]), "+f"(c[3])
        : "r"(a[0]), "r"(a[1]), "r"(a[2]), "r"(a[3]), "r"(b0), "r"(b1));
}

__device__ __forceinline__ void ldmx4(uint32_t* r, uint32_t addr) {
    asm volatile(
        "ldmatrix.sync.aligned.m8n8.x4.shared.b16 {%0,%1,%2,%3}, [%4];"
        : "=r"(r[0]), "=r"(r[1]), "=r"(r[2]), "=r"(r[3]) : "r"(addr));
}

__global__ __launch_bounds__(128, 8)
void s4_hmma_kernel(const float* __restrict__ Cin,        // [H, NH, 2]
                    const float* __restrict__ log_dt,     // [H]
                    const float* __restrict__ log_A_real, // [H, NH]
                    const float* __restrict__ A_imag,     // [H, NH]
                    float* __restrict__ out)              // [H, L]
{
    // 64 rows x 32 words (64 fp16) per tile, XOR swizzle: word = n ^ ((row&7)<<2)
    __shared__ uint32_t Ahi[64 * 32], Alo[64 * 32];
    __shared__ uint32_t Bt[64 * 32];

    const int h    = blockIdx.x;
    const int tid  = threadIdx.x;
    const int lane = tid & 31;
    const int w    = tid >> 5;

    // ---- phase 1: 4 chains x 8 steps per warp, balanced (verified) ----
    {
        const int n = lane;

        float dt   = __expf(log_dt[h]);
        float Are  = -__expf(log_A_real[h * NHn + n]);
        float Aim  = -A_imag[h * NHn + n];
        float dtar = Are * dt;
        float dtai = Aim * dt;

        float er = __expf(dtar);
        float sn, cs;
        __sincosf(dtai, &sn, &cs);
        float zr = er * cs, zi = er * sn;            // z = exp(dtA)

        // Cc = C * (z-1)/A
        float nr = zr - 1.0f, ni = zi;
        float inv = __fdividef(1.0f, Are * Are + Aim * Aim);
        float fr = (nr * Are + ni * Aim) * inv;
        float fi = (ni * Are - nr * Aim) * inv;
        float c0 = Cin[(h * NHn + n) * 2 + 0];
        float c1 = Cin[(h * NHn + n) * 2 + 1];
        float ccr = c0 * fr - c1 * fi;
        float cci = c0 * fi + c1 * fr;

        // anchors by repeated squaring
        #define CSQ(r_, i_) { float t_ = r_*r_ - i_*i_; i_ = 2.0f*r_*i_; r_ = t_; }
        float z8r = zr, z8i = zi;
        CSQ(z8r, z8i) CSQ(z8r, z8i) CSQ(z8r, z8i)               // z^8
        float z16r = z8r, z16i = z8i;  CSQ(z16r, z16i)          // z^16
        float z32r = z16r, z32i = z16i; CSQ(z32r, z32i)         // z^32
        float z64r = z32r, z64i = z32i; CSQ(z64r, z64i)         // z^64
        float z512r = z64r, z512i = z64i;
        CSQ(z512r, z512i) CSQ(z512r, z512i) CSQ(z512r, z512i)   // z^512
        float z1024r = z512r, z1024i = z512i; CSQ(z1024r, z1024i)   // z^1024
        float z2048r = z1024r, z2048i = z1024i; CSQ(z2048r, z2048i) // z^2048
        #undef CSQ

        // z^(16w): {1, z16, z32, z16*z32}
        float pwr, pwi;
        if (w == 0)      { pwr = 1.0f;  pwi = 0.0f;  }
        else if (w == 1) { pwr = z16r;  pwi = z16i;  }
        else if (w == 2) { pwr = z32r;  pwi = z32i;  }
        else             { pwr = z16r * z32r - z16i * z32i;
                           pwi = z16r * z32i + z16i * z32r; }

        // z^(1024w): {1, z1024, z2048, z1024*z2048}
        float awr, awi;
        if (w == 0)      { awr = 1.0f;   awi = 0.0f;   }
        else if (w == 1) { awr = z1024r; awi = z1024i; }
        else if (w == 2) { awr = z2048r; awi = z2048i; }
        else             { awr = z1024r * z2048r - z1024i * z2048i;
                           awi = z1024r * z2048i + z1024i * z2048r; }

        // chain starts
        float s0r = ccr * pwr - cci * pwi;           // B row 16w   : Cc z^(16w)
        float s0i = ccr * pwi + cci * pwr;
        float s1r = s0r * z8r - s0i * z8i;           // B row 16w+8
        float s1i = s0r * z8i + s0i * z8r;
        float t0r = awr, t0i = awi;                  // A row 16w   : z^(1024w)
        float t1r = awr * z512r - awi * z512i;       // A row 16w+8
        float t1i = awr * z512i + awi * z512r;

        const int rowB0 = w * 16, rowB1 = w * 16 + 8;

        #pragma unroll
        for (int i = 0; i < 8; i++) {
            int rb0 = rowB0 + i, rb1 = rowB1 + i;
            Bt[rb0 * 32 + (n ^ ((rb0 & 7) << 2))] = pack_h2(2.0f * s0r, -2.0f * s0i);
            Bt[rb1 * 32 + (n ^ ((rb1 & 7) << 2))] = pack_h2(2.0f * s1r, -2.0f * s1i);
            uint32_t hi, lo;
            split_h2(t0r, t0i, hi, lo);
            { int wo = rb0 * 32 + (n ^ ((rb0 & 7) << 2)); Ahi[wo] = hi; Alo[wo] = lo; }
            split_h2(t1r, t1i, hi, lo);
            { int wo = rb1 * 32 + (n ^ ((rb1 & 7) << 2)); Ahi[wo] = hi; Alo[wo] = lo; }

            float t;
            t = s0r * zr - s0i * zi;     s0i = s0r * zi + s0i * zr;     s0r = t;
            t = s1r * zr - s1i * zi;     s1i = s1r * zi + s1i * zr;     s1r = t;
            t = t0r * z64r - t0i * z64i; t0i = t0r * z64i + t0i * z64r; t0r = t;
            t = t1r * z64r - t1i * z64i; t1i = t1r * z64i + t1i * z64r; t1r = t;
        }
    }
    __syncthreads();

    // ---- phase 2: MMA with ldmatrix fragment loads ----
    const int lane8 = lane & 7;
    const int g     = lane >> 3;          // ldmatrix matrix-group 0..3
    const uint32_t swx = (uint32_t)lane8 << 2;

    uint32_t aHiBase = (uint32_t)__cvta_generic_to_shared(Ahi);
    uint32_t aLoBase = (uint32_t)__cvta_generic_to_shared(Alo);
    uint32_t bBase   = (uint32_t)__cvta_generic_to_shared(Bt);

    const uint32_t aRow  = (uint32_t)(w * 16 + ((g & 1) << 3) + lane8);
    const uint32_t aOff0 = (aRow << 5) << 2;
    const uint32_t aKsel = (uint32_t)((g >> 1) << 2);

    // B row-offsets (loop-invariant): pair p covers nt = 2p + (g>>1)
    const uint32_t bKsel = (uint32_t)((g & 1) << 2);
    uint32_t bOff0[4];
    #pragma unroll
    for (int p = 0; p < 4; p++) {
        uint32_t nt0 = (uint32_t)(2 * p + (g >> 1));
        uint32_t row = (nt0 << 3) + (uint32_t)lane8;
        bOff0[p] = (row << 5) << 2;
    }

    float acc[8][4];
    #pragma unroll
    for (int nt = 0; nt < 8; nt++)
        #pragma unroll
        for (int i = 0; i < 4; i++) acc[nt][i] = 0.0f;

    #pragma unroll
    for (int ks = 0; ks < 4; ks++) {
        uint32_t aw = (uint32_t)(ks * 8) + aKsel;
        uint32_t aoff = aOff0 + ((aw ^ swx) << 2);
        uint32_t ah[4], al[4];
        ldmx4(ah, aHiBase + aoff);
        ldmx4(al, aLoBase + aoff);

        uint32_t wc = (uint32_t)(ks * 8) + bKsel;
        uint32_t wcs = (wc ^ swx) << 2;

        // half 1: nt 0..3 (pairs 0,1)
        uint32_t b[8];
        ldmx4(&b[0], bBase + bOff0[0] + wcs);
        ldmx4(&b[4], bBase + bOff0[1] + wcs);
        #pragma unroll
        for (int nt = 0; nt < 4; nt++) {
            mma16816(acc[nt], ah, b[nt * 2], b[nt * 2 + 1]);
            mma16816(acc[nt], al, b[nt * 2], b[nt * 2 + 1]);
        }
        // half 2: nt 4..7 (pairs 2,3)
        ldmx4(&b[0], bBase + bOff0[2] + wcs);
        ldmx4(&b[4], bBase + bOff0[3] + wcs);
        #pragma unroll
        for (int nt = 0; nt < 4; nt++) {
            mma16816(acc[4 + nt], ah, b[nt * 2], b[nt * 2 + 1]);
            mma16816(acc[4 + nt], al, b[nt * 2], b[nt * 2 + 1]);
        }
    }

    // ---- epilogue: D(q, r) -> out[h, 64q + r] ----
    const int lane4 = lane >> 2;
    const int kq    = lane & 3;
    const int q0 = w * 16 + lane4, q1 = q0 + 8;
    const int cb = kq * 2;
    float* o = out + (size_t)h * Ll;
    #pragma unroll
    for (int nt = 0; nt < 8; nt++) {
        int c = nt * 8 + cb;
        *(float2*)&o[q0 * 64 + c] = make_float2(acc[nt][0], acc[nt][1]);
        *(float2*)&o[q1 * 64 + c] = make_float2(acc[nt][2], acc[nt][3]);
    }
}

extern "C" void kernel_launch(void* const* d_in, const int* in_sizes, int n_in,
                              void* d_out, int out_size)
{
    const float* C          = (const float*)d_in[0];   // [H, NH, 2]
    const float* log_dt     = (const float*)d_in[1];   // [H]
    const float* log_A_real = (const float*)d_in[2];   // [H, NH]
    const float* A_imag     = (const float*)d_in[3];   // [H, NH]
    float* out              = (float*)d_out;           // [H, L]

    s4_hmma_kernel<<<Hh, 128>>>(C, log_dt, log_A_real, A_imag, out);
}